// round 6
// baseline (speedup 1.0000x reference)
#include <cuda_runtime.h>
#include <cstdint>

#define BB 32
#define LL 1024
#define DD 128
#define BQ 32
#define KT 128
#define NT 256

#define S_FLOATS   (BQ * LL)                 // 32768 floats = 128 KB
#define TILE_F4    (KT * 33)                 // padded tile, 4224 float4 = 66 KB
#define Q_F4       (BQ * 32)                 // 1024 float4 = 16 KB
#define SMEM_BYTES (S_FLOATS * 4 + TILE_F4 * 16 + Q_F4 * 16)

// packed f32x2 helpers (PTX-only path; ptxas never auto-fuses)
__device__ __forceinline__ unsigned long long pk2(float lo, float hi) {
    unsigned long long r;
    asm("mov.b64 %0, {%1, %2};" : "=l"(r) : "f"(lo), "f"(hi));
    return r;
}
__device__ __forceinline__ float2 up2(unsigned long long v) {
    float2 r;
    asm("mov.b64 {%0, %1}, %2;" : "=f"(r.x), "=f"(r.y) : "l"(v));
    return r;
}
__device__ __forceinline__ void fma2(unsigned long long &a,
                                     unsigned long long x, unsigned long long y) {
    asm("fma.rn.f32x2 %0, %1, %2, %0;" : "+l"(a) : "l"(x), "l"(y));
}

__global__ __launch_bounds__(NT, 1)
void attn_neg_kernel(const float* __restrict__ Qg, const float* __restrict__ Kg,
                     const float* __restrict__ Vg, const float* __restrict__ scp,
                     const float* __restrict__ kg, float* __restrict__ outg)
{
    extern __shared__ float smem[];
    float*  S   = smem;                           // [BQ][LL]
    float4* T4  = (float4*)(smem + S_FLOATS);     // K/V tile [KT][33]
    float4* Qs4 = (float4*)(smem + S_FLOATS) + TILE_F4;  // [BQ][32]

    const int tid = threadIdx.x, warp = tid >> 5, lane = tid & 31;
    const int b = blockIdx.y, q0 = blockIdx.x * BQ;
    const int qr = warp * 4;                      // this warp's 4 q rows
    const float negscale = -scp[0];

    // ---- stage Q block ----
    {
        const float4* Qg4 = (const float4*)(Qg + ((size_t)b * LL + q0) * DD);
        #pragma unroll
        for (int i = 0; i < 4; i++) Qs4[tid + NT * i] = Qg4[tid + NT * i];
    }

    // ================= Phase 1: S = -scale * Q @ K^T =================
    {
        const float4* Kgl = (const float4*)(Kg + (size_t)b * LL * DD);
        float4 buf[16];
        #pragma unroll
        for (int i = 0; i < 16; i++) buf[i] = Kgl[tid + NT * i];

        for (int kt = 0; kt < LL / KT; kt++) {
            __syncthreads();
            #pragma unroll
            for (int i = 0; i < 16; i++) {
                int idx = tid + NT * i;
                T4[(idx >> 5) * 33 + (idx & 31)] = buf[i];
            }
            __syncthreads();
            if (kt + 1 < LL / KT) {
                #pragma unroll
                for (int i = 0; i < 16; i++)
                    buf[i] = Kgl[(kt + 1) * (KT * DD / 4) + tid + NT * i];
            }

            unsigned long long acc[4][2];
            #pragma unroll
            for (int i = 0; i < 4; i++) { acc[i][0] = 0ull; acc[i][1] = 0ull; }

            #pragma unroll 4
            for (int d4 = 0; d4 < 32; d4++) {
                float4 k0 = T4[(lane      ) * 33 + d4];
                float4 k1 = T4[(lane + 32 ) * 33 + d4];
                float4 k2 = T4[(lane + 64 ) * 33 + d4];
                float4 k3 = T4[(lane + 96 ) * 33 + d4];
                unsigned long long ax = pk2(k0.x, k1.x), bx = pk2(k2.x, k3.x);
                unsigned long long ay = pk2(k0.y, k1.y), by = pk2(k2.y, k3.y);
                unsigned long long az = pk2(k0.z, k1.z), bz = pk2(k2.z, k3.z);
                unsigned long long aw = pk2(k0.w, k1.w), bw = pk2(k2.w, k3.w);
                #pragma unroll
                for (int i = 0; i < 4; i++) {
                    float4 qv = Qs4[(qr + i) * 32 + d4];     // warp-broadcast
                    unsigned long long qx = pk2(qv.x, qv.x), qy = pk2(qv.y, qv.y);
                    unsigned long long qz = pk2(qv.z, qv.z), qw = pk2(qv.w, qv.w);
                    fma2(acc[i][0], qx, ax);  fma2(acc[i][1], qx, bx);
                    fma2(acc[i][0], qy, ay);  fma2(acc[i][1], qy, by);
                    fma2(acc[i][0], qz, az);  fma2(acc[i][1], qz, bz);
                    fma2(acc[i][0], qw, aw);  fma2(acc[i][1], qw, bw);
                }
            }
            #pragma unroll
            for (int i = 0; i < 4; i++) {
                float* sp = S + (qr + i) * LL + kt * KT + lane;
                float2 a0 = up2(acc[i][0]), a1 = up2(acc[i][1]);
                sp[0] = a0.x * negscale;  sp[32] = a0.y * negscale;
                sp[64] = a1.x * negscale; sp[96] = a1.y * negscale;
            }
        }
    }

    // ================= Phase 2: beta = softmax(-softmax(S) * kg) =================
    // t = -p*kg lies in [-1,0] -> second softmax max pass skipped (m2=0).
    #pragma unroll 1
    for (int r = 0; r < 4; r++) {
        const int q = qr + r;
        float* Srow = S + q * LL;
        const float* kgrow = kg + ((size_t)b * LL + (q0 + q)) * LL;

        float m1 = -1e30f;
        #pragma unroll 8
        for (int i = 0; i < 32; i++) m1 = fmaxf(m1, Srow[lane + 32 * i]);
        #pragma unroll
        for (int o = 16; o; o >>= 1) m1 = fmaxf(m1, __shfl_xor_sync(~0u, m1, o));

        float z1 = 0.f;
        #pragma unroll 8
        for (int i = 0; i < 32; i++) z1 += __expf(Srow[lane + 32 * i] - m1);
        #pragma unroll
        for (int o = 16; o; o >>= 1) z1 += __shfl_xor_sync(~0u, z1, o);
        const float inv1 = 1.0f / z1;

        float z2 = 0.f;
        #pragma unroll 8
        for (int i = 0; i < 32; i++) {
            int c = lane + 32 * i;
            float t = -__expf(Srow[c] - m1) * inv1 * kgrow[c];
            float e = __expf(t);
            Srow[c] = e;
            z2 += e;
        }
        #pragma unroll
        for (int o = 16; o; o >>= 1) z2 += __shfl_xor_sync(~0u, z2, o);
        const float inv2 = 1.0f / z2;
        #pragma unroll 8
        for (int i = 0; i < 32; i++) Srow[lane + 32 * i] *= inv2;
    }

    // ================= Phase 3: out = beta @ V =================
    {
        const float4* Vgl = (const float4*)(Vg + (size_t)b * LL * DD);
        float4 buf[16];
        #pragma unroll
        for (int i = 0; i < 16; i++) buf[i] = Vgl[tid + NT * i];

        unsigned long long acc[4][2];
        #pragma unroll
        for (int i = 0; i < 4; i++) { acc[i][0] = 0ull; acc[i][1] = 0ull; }

        for (int vt = 0; vt < LL / KT; vt++) {
            __syncthreads();
            #pragma unroll
            for (int i = 0; i < 16; i++) {
                int idx = tid + NT * i;
                T4[(idx >> 5) * 33 + (idx & 31)] = buf[i];
            }
            __syncthreads();
            if (vt + 1 < LL / KT) {
                #pragma unroll
                for (int i = 0; i < 16; i++)
                    buf[i] = Vgl[(vt + 1) * (KT * DD / 4) + tid + NT * i];
            }

            #pragma unroll 2
            for (int k = 0; k < KT; k += 4) {
                float4 v0 = T4[(k + 0) * 33 + lane];
                float4 v1 = T4[(k + 1) * 33 + lane];
                float4 v2 = T4[(k + 2) * 33 + lane];
                float4 v3 = T4[(k + 3) * 33 + lane];
                unsigned long long v0a = pk2(v0.x, v0.y), v0b = pk2(v0.z, v0.w);
                unsigned long long v1a = pk2(v1.x, v1.y), v1b = pk2(v1.z, v1.w);
                unsigned long long v2a = pk2(v2.x, v2.y), v2b = pk2(v2.z, v2.w);
                unsigned long long v3a = pk2(v3.x, v3.y), v3b = pk2(v3.z, v3.w);
                #pragma unroll
                for (int i = 0; i < 4; i++) {
                    float4 bq = ((const float4*)(S + (qr + i) * LL + vt * KT))[k >> 2]; // uniform
                    unsigned long long b0 = pk2(bq.x, bq.x), b1 = pk2(bq.y, bq.y);
                    unsigned long long b2 = pk2(bq.z, bq.z), b3 = pk2(bq.w, bq.w);
                    fma2(acc[i][0], b0, v0a);  fma2(acc[i][1], b0, v0b);
                    fma2(acc[i][0], b1, v1a);  fma2(acc[i][1], b1, v1b);
                    fma2(acc[i][0], b2, v2a);  fma2(acc[i][1], b2, v2b);
                    fma2(acc[i][0], b3, v3a);  fma2(acc[i][1], b3, v3b);
                }
            }
        }

        float4* out4 = (float4*)outg;
        #pragma unroll
        for (int i = 0; i < 4; i++) {
            float2 a0 = up2(acc[i][0]), a1 = up2(acc[i][1]);
            float4 o; o.x = a0.x; o.y = a0.y; o.z = a1.x; o.w = a1.y;
            out4[((size_t)b * LL + q0 + qr + i) * (DD / 4) + lane] = o;
        }
    }
}

extern "C" void kernel_launch(void* const* d_in, const int* in_sizes, int n_in,
                              void* d_out, int out_size) {
    const float* Q  = (const float*)d_in[0];
    const float* K  = (const float*)d_in[1];
    const float* V  = (const float*)d_in[2];
    const float* sc = (const float*)d_in[3];
    const float* kg = (const float*)d_in[4];
    float* out = (float*)d_out;
    (void)in_sizes; (void)n_in; (void)out_size;

    cudaFuncSetAttribute(attn_neg_kernel,
                         cudaFuncAttributeMaxDynamicSharedMemorySize, SMEM_BYTES);
    dim3 grid(LL / BQ, BB);
    attn_neg_kernel<<<grid, NT, SMEM_BYTES>>>(Q, K, V, sc, kg, out);
}